// round 8
// baseline (speedup 1.0000x reference)
#include <cuda_runtime.h>
#include <cstdint>

// Problem constants (fixed by the dataset: x [32,256,512], embeddings [8192,512])
#define N_TOK   8192
#define K_CODES 8192
#define DIM     512

// Tiling for the argmin-GEMM
#define TM 64      // token rows per block
#define TN 128     // codes per k-chunk
#define TD 32      // D-slice per smem stage
#define SPLITS 4   // K split for grid parallelism
#define KS (K_CODES / SPLITS)

// ---------------- device scratch (no allocations allowed) ----------------
// Referenced ONLY from device code (host-side use of a __device__ symbol is the
// host shadow address -> UVM pool allocation -> harness mem-guard failure).
__device__ float g_esq[K_CODES];
__device__ float g_xsq[N_TOK];
__device__ float g_pval[SPLITS][N_TOK];
__device__ int   g_pidx[SPLITS][N_TOK];
__device__ float g_rowsq[N_TOK];

// ---------------- packed f32x2 helpers (sm_100a Blackwell) ----------------
// Each 32-bit lane of fma.rn.f32x2 is an independent IEEE fp32 FMA, so a packed
// accumulator chain over ascending d is bit-identical to a scalar FFMA chain.
__device__ __forceinline__ unsigned long long pack2(float a, float b) {
    unsigned long long r;
    asm("mov.b64 %0, {%1, %2};" : "=l"(r) : "f"(a), "f"(b));
    return r;
}
__device__ __forceinline__ void unpack2(unsigned long long v, float& a, float& b) {
    asm("mov.b64 {%0, %1}, %2;" : "=f"(a), "=f"(b) : "l"(v));
}
__device__ __forceinline__ unsigned long long fma2(unsigned long long a,
                                                   unsigned long long b,
                                                   unsigned long long c) {
    unsigned long long d;
    asm("fma.rn.f32x2 %0, %1, %2, %3;" : "=l"(d) : "l"(a), "l"(b), "l"(c));
    return d;
}

// ---------------- kernel 1a: e_sq[k] = sum_d E[k][d]^2 ----------------
// Replicates XLA row-reduce codegen: lane-strided (stride 32) ascending
// accumulation with NON-FUSED mul+add (HLO is mul, then reduce), then a
// butterfly tree (lane 0's combine order equals shfl-down's).
__global__ void vq_esq(const float* __restrict__ E) {
    int w = (blockIdx.x * blockDim.x + threadIdx.x) >> 5;
    int lane = threadIdx.x & 31;
    if (w >= K_CODES) return;
    const float* row = E + (size_t)w * DIM;
    float s = 0.f;
    #pragma unroll
    for (int d = lane; d < DIM; d += 32) {
        float v = __ldg(row + d);
        s = __fadd_rn(s, __fmul_rn(v, v));
    }
    #pragma unroll
    for (int o = 16; o > 0; o >>= 1) s = __fadd_rn(s, __shfl_xor_sync(0xffffffffu, s, o));
    if (lane == 0) g_esq[w] = s;
}

// ---------------- kernel 1b: x_sq[n] = sum_d x[n][d]^2 ----------------
__global__ void vq_xsq(const float* __restrict__ x) {
    int w = (blockIdx.x * blockDim.x + threadIdx.x) >> 5;
    int lane = threadIdx.x & 31;
    if (w >= N_TOK) return;
    const float* row = x + (size_t)w * DIM;
    float s = 0.f;
    #pragma unroll
    for (int d = lane; d < DIM; d += 32) {
        float v = __ldg(row + d);
        s = __fadd_rn(s, __fmul_rn(v, v));
    }
    #pragma unroll
    for (int o = 16; o > 0; o >>= 1) s = __fadd_rn(s, __shfl_xor_sync(0xffffffffu, s, o));
    if (lane == 0) g_xsq[w] = s;
}

// ---------------- kernel 2: fused fp32-dot + reference-rounded distance + argmin ----------------
// Block = 256 threads = 16(tx) x 16(ty). Each thread owns 4 rows x 8 cols.
// dot: single fp32 FFMA accumulator chain over d ascending (SGEMM-equivalent bits).
// dist[n][k] = fl( fl(x_sq[n] - 2*dot) + e_sq[k] )  -- 2*dot exact, fmaf = the sub's single rounding.
__global__ __launch_bounds__(256) void vq_argmin(const float* __restrict__ x,
                                                 const float* __restrict__ E) {
    __shared__ float xs[TD][TM + 1];   // transposed x tile
    __shared__ float es[TD][TN + 2];   // transposed, pair-interleaved e tile
    __shared__ float rv[TM][16];
    __shared__ int   ri[TM][16];

    const int t  = threadIdx.x;
    const int tx = t & 15;
    const int ty = t >> 4;
    const int mtile = blockIdx.x >> 2;          // 0..127
    const int split = blockIdx.x & (SPLITS - 1);
    const int m0 = mtile * TM;
    const int kbase = split * KS;

    const int ld_d = t & 31;   // d within slice
    const int ld_r = t >> 5;   // row group

    float xsqv[4];
    #pragma unroll
    for (int i = 0; i < 4; i++) xsqv[i] = g_xsq[m0 + ty * 4 + i];

    float bestv[4] = {3.4e38f, 3.4e38f, 3.4e38f, 3.4e38f};
    int   besti[4] = {0, 0, 0, 0};

    const unsigned long long zero2 = pack2(0.f, 0.f);

    for (int kc = 0; kc < KS; kc += TN) {
        const int k0 = kbase + kc;

        unsigned long long acc[4][4];
        #pragma unroll
        for (int i = 0; i < 4; i++)
            #pragma unroll
            for (int j = 0; j < 4; j++) acc[i][j] = zero2;

        for (int d0 = 0; d0 < DIM; d0 += TD) {
            __syncthreads();
            // load x tile (64 x 32), coalesced, transposed store
            #pragma unroll
            for (int i = 0; i < TM / 8; i++) {
                int m = ld_r + i * 8;
                xs[ld_d][m] = x[(size_t)(m0 + m) * DIM + d0 + ld_d];
            }
            // load e tile (128 x 32), transposed + pair-interleaved:
            // col c -> flat pos = ((c>>1)&3)*32 + ((c>>3)<<1) + (c&1)
            #pragma unroll
            for (int i = 0; i < TN / 8; i++) {
                int c = ld_r + i * 8;
                int pos = ((c >> 1) & 3) * 32 + ((c >> 3) << 1) + (c & 1);
                es[ld_d][pos] = E[(size_t)(k0 + c) * DIM + d0 + ld_d];
            }
            __syncthreads();

            #pragma unroll
            for (int d = 0; d < TD; d++) {
                unsigned long long xp[4], ep[4];
                #pragma unroll
                for (int i = 0; i < 4; i++) {
                    float v = xs[d][ty * 4 + i];
                    xp[i] = pack2(v, v);
                }
                #pragma unroll
                for (int j = 0; j < 4; j++) {
                    float2 e2 = *reinterpret_cast<const float2*>(&es[d][j * 32 + tx * 2]);
                    ep[j] = pack2(e2.x, e2.y);
                }
                #pragma unroll
                for (int i = 0; i < 4; i++)
                    #pragma unroll
                    for (int j = 0; j < 4; j++)
                        acc[i][j] = fma2(xp[i], ep[j], acc[i][j]);
            }
        }

        // epilogue: dist = fl( fl(x_sq - 2*dot) + e_sq )
        // ascending-k strict-< updates give first-index semantics on exact ties.
        #pragma unroll
        for (int j = 0; j < 4; j++) {
            int kk = k0 + 8 * tx + 2 * j;
            float eq0 = __ldg(&g_esq[kk]);
            float eq1 = __ldg(&g_esq[kk + 1]);
            #pragma unroll
            for (int i = 0; i < 4; i++) {
                float a0, a1;
                unpack2(acc[i][j], a0, a1);
                float t0 = fmaf(-2.f, a0, xsqv[i]);
                float t1 = fmaf(-2.f, a1, xsqv[i]);
                float s0 = __fadd_rn(t0, eq0);
                float s1 = __fadd_rn(t1, eq1);
                if (s0 < bestv[i]) { bestv[i] = s0; besti[i] = kk; }
                if (s1 < bestv[i]) { bestv[i] = s1; besti[i] = kk + 1; }
            }
        }
    }

    __syncthreads();
    #pragma unroll
    for (int i = 0; i < 4; i++) {
        rv[ty * 4 + i][tx] = bestv[i];
        ri[ty * 4 + i][tx] = besti[i];
    }
    __syncthreads();
    if (t < TM) {
        float bv = rv[t][0];
        int   bi = ri[t][0];
        #pragma unroll
        for (int j = 1; j < 16; j++) {
            float v = rv[t][j];
            int idx = ri[t][j];
            if (v < bv || (v == bv && idx < bi)) { bv = v; bi = idx; }
        }
        g_pval[split][m0 + t] = bv;
        g_pidx[split][m0 + t] = bi;
    }
}

// ---------------- kernel 3: combine splits, gather, write q_st + indices ----------------
__global__ void vq_combine(const float* __restrict__ x, const float* __restrict__ E,
                           float* __restrict__ out) {
    int gw   = (blockIdx.x * blockDim.x + threadIdx.x) >> 5;  // one warp per token row
    int lane = threadIdx.x & 31;
    if (gw >= N_TOK) return;

    float bv = g_pval[0][gw];
    int   bi = g_pidx[0][gw];
    #pragma unroll
    for (int s = 1; s < SPLITS; s++) {
        float v = g_pval[s][gw];
        int idx = g_pidx[s][gw];
        if (v < bv || (v == bv && idx < bi)) { bv = v; bi = idx; }
    }

    const float* er = E + (size_t)bi * DIM;
    const float* xr = x + (size_t)gw * DIM;
    float* qr = out + (size_t)gw * DIM;
    float sq = 0.f;
    #pragma unroll
    for (int d = lane; d < DIM; d += 32) {
        float e  = er[d];
        float xv = xr[d];
        qr[d] = __fadd_rn(xv, __fadd_rn(e, -xv));  // straight-through: fl(x + fl(q - x))
        float df = __fadd_rn(xv, -e);
        sq = __fadd_rn(sq, __fmul_rn(df, df));
    }
    #pragma unroll
    for (int o = 16; o > 0; o >>= 1) sq = __fadd_rn(sq, __shfl_xor_sync(0xffffffffu, sq, o));
    if (lane == 0) {
        g_rowsq[gw] = sq;
        out[(size_t)N_TOK * DIM + gw] = (float)bi;   // indices as float32
    }
}

// ---------------- kernel 4: deterministic loss reduction ----------------
__global__ void vq_loss(float* __restrict__ out) {
    __shared__ float red[256];
    int t = threadIdx.x;
    float s = 0.f;
    for (int i = t; i < N_TOK; i += 256) s += g_rowsq[i];
    red[t] = s;
    __syncthreads();
    #pragma unroll
    for (int o = 128; o > 0; o >>= 1) {
        if (t < o) red[t] += red[t + o];
        __syncthreads();
    }
    if (t == 0) {
        float mse = red[0] / (float)((size_t)N_TOK * DIM);
        size_t base = (size_t)N_TOK * DIM + N_TOK;
        out[base + 0] = 0.25f * mse;   // commitment_loss
        out[base + 1] = mse;           // codebook_loss
        out[base + 2] = 1.25f * mse;   // total_loss
    }
}

// ---------------- entry point ----------------
extern "C" void kernel_launch(void* const* d_in, const int* in_sizes, int n_in,
                              void* d_out, int out_size) {
    (void)in_sizes; (void)n_in; (void)out_size;
    const float* x = (const float*)d_in[0];   // [32*256, 512]
    const float* E = (const float*)d_in[1];   // [8192, 512]
    float* out = (float*)d_out;

    vq_esq<<<K_CODES * 32 / 256, 256>>>(E);
    vq_xsq<<<N_TOK * 32 / 256, 256>>>(x);
    vq_argmin<<<(N_TOK / TM) * SPLITS, 256>>>(x, E);
    vq_combine<<<N_TOK * 32 / 256, 256>>>(x, E, out);
    vq_loss<<<1, 256>>>(out);
}

// round 9
// speedup vs baseline: 1.0000x; 1.0000x over previous
#include <cuda_runtime.h>
#include <cstdint>

// Problem constants (fixed by the dataset: x [32,256,512], embeddings [8192,512])
#define N_TOK   8192
#define K_CODES 8192
#define DIM     512

// Tiling for the argmin-GEMM
#define TM 64      // token rows per block
#define TN 128     // codes per k-chunk
#define TD 32      // D-slice per smem stage
#define SPLITS 4   // K split for grid parallelism
#define KS (K_CODES / SPLITS)

// ---------------- device scratch (no allocations allowed) ----------------
// Referenced ONLY from device code (host-side use of a __device__ symbol is the
// host shadow address -> UVM pool allocation -> harness mem-guard failure).
__device__ float g_esq[K_CODES];
__device__ float g_xsq[N_TOK];
__device__ float g_pval[SPLITS][N_TOK];
__device__ int   g_pidx[SPLITS][N_TOK];
__device__ float g_rowsq[N_TOK];

// ---------------- packed f32x2 helpers (sm_100a Blackwell) ----------------
// Each 32-bit lane of fma.rn.f32x2 is an independent IEEE fp32 FMA, so a packed
// accumulator chain over ascending d is bit-identical to a scalar FFMA chain.
__device__ __forceinline__ unsigned long long pack2(float a, float b) {
    unsigned long long r;
    asm("mov.b64 %0, {%1, %2};" : "=l"(r) : "f"(a), "f"(b));
    return r;
}
__device__ __forceinline__ void unpack2(unsigned long long v, float& a, float& b) {
    asm("mov.b64 {%0, %1}, %2;" : "=f"(a), "=f"(b) : "l"(v));
}
__device__ __forceinline__ unsigned long long fma2(unsigned long long a,
                                                   unsigned long long b,
                                                   unsigned long long c) {
    unsigned long long d;
    asm("fma.rn.f32x2 %0, %1, %2, %3;" : "=l"(d) : "l"(a), "l"(b), "l"(c));
    return d;
}

// ---------------- kernel 1a: e_sq[k] = sum_d E[k][d]^2 ----------------
// Replicates XLA row-reduce codegen: lane-strided (stride 32) ascending
// accumulation with NON-FUSED mul+add (HLO is mul, then reduce), then a
// butterfly tree (lane 0's combine order equals shfl-down's).
__global__ void vq_esq(const float* __restrict__ E) {
    int w = (blockIdx.x * blockDim.x + threadIdx.x) >> 5;
    int lane = threadIdx.x & 31;
    if (w >= K_CODES) return;
    const float* row = E + (size_t)w * DIM;
    float s = 0.f;
    #pragma unroll
    for (int d = lane; d < DIM; d += 32) {
        float v = __ldg(row + d);
        s = __fadd_rn(s, __fmul_rn(v, v));
    }
    #pragma unroll
    for (int o = 16; o > 0; o >>= 1) s = __fadd_rn(s, __shfl_xor_sync(0xffffffffu, s, o));
    if (lane == 0) g_esq[w] = s;
}

// ---------------- kernel 1b: x_sq[n] = sum_d x[n][d]^2 ----------------
__global__ void vq_xsq(const float* __restrict__ x) {
    int w = (blockIdx.x * blockDim.x + threadIdx.x) >> 5;
    int lane = threadIdx.x & 31;
    if (w >= N_TOK) return;
    const float* row = x + (size_t)w * DIM;
    float s = 0.f;
    #pragma unroll
    for (int d = lane; d < DIM; d += 32) {
        float v = __ldg(row + d);
        s = __fadd_rn(s, __fmul_rn(v, v));
    }
    #pragma unroll
    for (int o = 16; o > 0; o >>= 1) s = __fadd_rn(s, __shfl_xor_sync(0xffffffffu, s, o));
    if (lane == 0) g_xsq[w] = s;
}

// ---------------- kernel 2: fused fp32-dot + reference-rounded distance + argmin ----------------
// Block = 256 threads = 16(tx) x 16(ty). Each thread owns 4 rows x 8 cols.
// dot: single fp32 FFMA accumulator chain over d ascending (SGEMM-equivalent bits).
// dist[n][k] = fl( fl(x_sq[n] - 2*dot) + e_sq[k] )  -- 2*dot exact, fmaf = the sub's single rounding.
__global__ __launch_bounds__(256) void vq_argmin(const float* __restrict__ x,
                                                 const float* __restrict__ E) {
    __shared__ float xs[TD][TM + 1];   // transposed x tile
    __shared__ float es[TD][TN + 2];   // transposed, pair-interleaved e tile
    __shared__ float rv[TM][16];
    __shared__ int   ri[TM][16];

    const int t  = threadIdx.x;
    const int tx = t & 15;
    const int ty = t >> 4;
    const int mtile = blockIdx.x >> 2;          // 0..127
    const int split = blockIdx.x & (SPLITS - 1);
    const int m0 = mtile * TM;
    const int kbase = split * KS;

    const int ld_d = t & 31;   // d within slice
    const int ld_r = t >> 5;   // row group

    float xsqv[4];
    #pragma unroll
    for (int i = 0; i < 4; i++) xsqv[i] = g_xsq[m0 + ty * 4 + i];

    float bestv[4] = {3.4e38f, 3.4e38f, 3.4e38f, 3.4e38f};
    int   besti[4] = {0, 0, 0, 0};

    const unsigned long long zero2 = pack2(0.f, 0.f);

    for (int kc = 0; kc < KS; kc += TN) {
        const int k0 = kbase + kc;

        unsigned long long acc[4][4];
        #pragma unroll
        for (int i = 0; i < 4; i++)
            #pragma unroll
            for (int j = 0; j < 4; j++) acc[i][j] = zero2;

        for (int d0 = 0; d0 < DIM; d0 += TD) {
            __syncthreads();
            // load x tile (64 x 32), coalesced, transposed store
            #pragma unroll
            for (int i = 0; i < TM / 8; i++) {
                int m = ld_r + i * 8;
                xs[ld_d][m] = x[(size_t)(m0 + m) * DIM + d0 + ld_d];
            }
            // load e tile (128 x 32), transposed + pair-interleaved:
            // col c -> flat pos = ((c>>1)&3)*32 + ((c>>3)<<1) + (c&1)
            #pragma unroll
            for (int i = 0; i < TN / 8; i++) {
                int c = ld_r + i * 8;
                int pos = ((c >> 1) & 3) * 32 + ((c >> 3) << 1) + (c & 1);
                es[ld_d][pos] = E[(size_t)(k0 + c) * DIM + d0 + ld_d];
            }
            __syncthreads();

            #pragma unroll
            for (int d = 0; d < TD; d++) {
                unsigned long long xp[4], ep[4];
                #pragma unroll
                for (int i = 0; i < 4; i++) {
                    float v = xs[d][ty * 4 + i];
                    xp[i] = pack2(v, v);
                }
                #pragma unroll
                for (int j = 0; j < 4; j++) {
                    float2 e2 = *reinterpret_cast<const float2*>(&es[d][j * 32 + tx * 2]);
                    ep[j] = pack2(e2.x, e2.y);
                }
                #pragma unroll
                for (int i = 0; i < 4; i++)
                    #pragma unroll
                    for (int j = 0; j < 4; j++)
                        acc[i][j] = fma2(xp[i], ep[j], acc[i][j]);
            }
        }

        // epilogue: dist = fl( fl(x_sq - 2*dot) + e_sq )
        // ascending-k strict-< updates give first-index semantics on exact ties.
        #pragma unroll
        for (int j = 0; j < 4; j++) {
            int kk = k0 + 8 * tx + 2 * j;
            float eq0 = __ldg(&g_esq[kk]);
            float eq1 = __ldg(&g_esq[kk + 1]);
            #pragma unroll
            for (int i = 0; i < 4; i++) {
                float a0, a1;
                unpack2(acc[i][j], a0, a1);
                float t0 = fmaf(-2.f, a0, xsqv[i]);
                float t1 = fmaf(-2.f, a1, xsqv[i]);
                float s0 = __fadd_rn(t0, eq0);
                float s1 = __fadd_rn(t1, eq1);
                if (s0 < bestv[i]) { bestv[i] = s0; besti[i] = kk; }
                if (s1 < bestv[i]) { bestv[i] = s1; besti[i] = kk + 1; }
            }
        }
    }

    __syncthreads();
    #pragma unroll
    for (int i = 0; i < 4; i++) {
        rv[ty * 4 + i][tx] = bestv[i];
        ri[ty * 4 + i][tx] = besti[i];
    }
    __syncthreads();
    if (t < TM) {
        float bv = rv[t][0];
        int   bi = ri[t][0];
        #pragma unroll
        for (int j = 1; j < 16; j++) {
            float v = rv[t][j];
            int idx = ri[t][j];
            if (v < bv || (v == bv && idx < bi)) { bv = v; bi = idx; }
        }
        g_pval[split][m0 + t] = bv;
        g_pidx[split][m0 + t] = bi;
    }
}

// ---------------- kernel 3: combine splits, gather, write q_st + indices ----------------
__global__ void vq_combine(const float* __restrict__ x, const float* __restrict__ E,
                           float* __restrict__ out) {
    int gw   = (blockIdx.x * blockDim.x + threadIdx.x) >> 5;  // one warp per token row
    int lane = threadIdx.x & 31;
    if (gw >= N_TOK) return;

    float bv = g_pval[0][gw];
    int   bi = g_pidx[0][gw];
    #pragma unroll
    for (int s = 1; s < SPLITS; s++) {
        float v = g_pval[s][gw];
        int idx = g_pidx[s][gw];
        if (v < bv || (v == bv && idx < bi)) { bv = v; bi = idx; }
    }

    const float* er = E + (size_t)bi * DIM;
    const float* xr = x + (size_t)gw * DIM;
    float* qr = out + (size_t)gw * DIM;
    float sq = 0.f;
    #pragma unroll
    for (int d = lane; d < DIM; d += 32) {
        float e  = er[d];
        float xv = xr[d];
        qr[d] = __fadd_rn(xv, __fadd_rn(e, -xv));  // straight-through: fl(x + fl(q - x))
        float df = __fadd_rn(xv, -e);
        sq = __fadd_rn(sq, __fmul_rn(df, df));
    }
    #pragma unroll
    for (int o = 16; o > 0; o >>= 1) sq = __fadd_rn(sq, __shfl_xor_sync(0xffffffffu, sq, o));
    if (lane == 0) {
        g_rowsq[gw] = sq;
        out[(size_t)N_TOK * DIM + gw] = (float)bi;   // indices as float32
    }
}

// ---------------- kernel 4: deterministic loss reduction ----------------
__global__ void vq_loss(float* __restrict__ out) {
    __shared__ float red[256];
    int t = threadIdx.x;
    float s = 0.f;
    for (int i = t; i < N_TOK; i += 256) s += g_rowsq[i];
    red[t] = s;
    __syncthreads();
    #pragma unroll
    for (int o = 128; o > 0; o >>= 1) {
        if (t < o) red[t] += red[t + o];
        __syncthreads();
    }
    if (t == 0) {
        float mse = red[0] / (float)((size_t)N_TOK * DIM);
        size_t base = (size_t)N_TOK * DIM + N_TOK;
        out[base + 0] = 0.25f * mse;   // commitment_loss
        out[base + 1] = mse;           // codebook_loss
        out[base + 2] = 1.25f * mse;   // total_loss
    }
}

// ---------------- entry point ----------------
extern "C" void kernel_launch(void* const* d_in, const int* in_sizes, int n_in,
                              void* d_out, int out_size) {
    (void)in_sizes; (void)n_in; (void)out_size;
    const float* x = (const float*)d_in[0];   // [32*256, 512]
    const float* E = (const float*)d_in[1];   // [8192, 512]
    float* out = (float*)d_out;

    vq_esq<<<K_CODES * 32 / 256, 256>>>(E);
    vq_xsq<<<N_TOK * 32 / 256, 256>>>(x);
    vq_argmin<<<(N_TOK / TM) * SPLITS, 256>>>(x, E);
    vq_combine<<<N_TOK * 32 / 256, 256>>>(x, E, out);
    vq_loss<<<1, 256>>>(out);
}

// round 10
// speedup vs baseline: 1.0453x; 1.0453x over previous
#include <cuda_runtime.h>
#include <cstdint>

// Problem constants (fixed by the dataset: x [32,256,512], embeddings [8192,512])
#define N_TOK   8192
#define K_CODES 8192
#define DIM     512

// Argmin-GEMM tiling: persistent blocks, items = (mtile, split)
#define TM 128       // token rows per item
#define TN 128       // codes per k-chunk
#define TD 32        // D-slice per smem stage
#define SPLITS 16    // K splits (item granularity for load balance)
#define KS (K_CODES / SPLITS)        // 512
#define NCHUNK (KS / TN)             // 4
#define NSTAGE (DIM / TD)            // 16
#define MTILES (N_TOK / TM)          // 64
#define ITEMS (MTILES * SPLITS)      // 1024
#define GRID_PERSIST 148

// ---------------- device scratch (no allocations allowed) ----------------
// Referenced ONLY from device code (host-side use of a __device__ symbol is the
// host shadow address -> UVM pool allocation -> harness mem-guard failure).
__device__ float g_esq[K_CODES];
__device__ float g_xsq[N_TOK];
__device__ float g_pval[SPLITS][N_TOK];
__device__ int   g_pidx[SPLITS][N_TOK];
__device__ float g_rowsq[N_TOK];

// ---------------- packed f32x2 helpers (sm_100a Blackwell) ----------------
// Each 32-bit lane of fma.rn.f32x2 is an independent IEEE fp32 FMA, so a packed
// accumulator chain over ascending d is bit-identical to a scalar FFMA chain.
__device__ __forceinline__ unsigned long long pack2(float a, float b) {
    unsigned long long r;
    asm("mov.b64 %0, {%1, %2};" : "=l"(r) : "f"(a), "f"(b));
    return r;
}
__device__ __forceinline__ void unpack2(unsigned long long v, float& a, float& b) {
    asm("mov.b64 {%0, %1}, %2;" : "=f"(a), "=f"(b) : "l"(v));
}
__device__ __forceinline__ unsigned long long fma2(unsigned long long a,
                                                   unsigned long long b,
                                                   unsigned long long c) {
    unsigned long long d;
    asm("fma.rn.f32x2 %0, %1, %2, %3;" : "=l"(d) : "l"(a), "l"(b), "l"(c));
    return d;
}

// ---------------- kernel 1a: e_sq[k] = sum_d E[k][d]^2 ----------------
// XLA row-reduce replica: lane-strided ascending accumulation, NON-FUSED
// mul+add, butterfly tree. (Verified bit-exact in R9.)
__global__ void vq_esq(const float* __restrict__ E) {
    int w = (blockIdx.x * blockDim.x + threadIdx.x) >> 5;
    int lane = threadIdx.x & 31;
    if (w >= K_CODES) return;
    const float* row = E + (size_t)w * DIM;
    float s = 0.f;
    #pragma unroll
    for (int d = lane; d < DIM; d += 32) {
        float v = __ldg(row + d);
        s = __fadd_rn(s, __fmul_rn(v, v));
    }
    #pragma unroll
    for (int o = 16; o > 0; o >>= 1) s = __fadd_rn(s, __shfl_xor_sync(0xffffffffu, s, o));
    if (lane == 0) g_esq[w] = s;
}

// ---------------- kernel 1b: x_sq[n] = sum_d x[n][d]^2 ----------------
__global__ void vq_xsq(const float* __restrict__ x) {
    int w = (blockIdx.x * blockDim.x + threadIdx.x) >> 5;
    int lane = threadIdx.x & 31;
    if (w >= N_TOK) return;
    const float* row = x + (size_t)w * DIM;
    float s = 0.f;
    #pragma unroll
    for (int d = lane; d < DIM; d += 32) {
        float v = __ldg(row + d);
        s = __fadd_rn(s, __fmul_rn(v, v));
    }
    #pragma unroll
    for (int o = 16; o > 0; o >>= 1) s = __fadd_rn(s, __shfl_xor_sync(0xffffffffu, s, o));
    if (lane == 0) g_xsq[w] = s;
}

// ---------------- kernel 2: persistent fused fp32-dot + argmin ----------------
// 148 blocks x 256 threads, static round-robin over 1024 (mtile, split) items.
// Thread tile 8x8 via pair-x-pair packed FMA:
//   accD[q][p] lanes = (r0*c0, r1*c1), accA[q][p] lanes = (r0*c1, r1*c0)
// Every lane is a serial ascending-d fp32 FMA chain -> bit-identical to R9.
// dist[n][k] = fl( fl(x_sq[n] - 2*dot) + e_sq[k] ), first-index tie-break.
__global__ __launch_bounds__(256) void vq_argmin(const float* __restrict__ x,
                                                 const float* __restrict__ E) {
    __shared__ float xs[TD][TM + 2];   // transposed x tile (stride 130, even)
    __shared__ float es[TD][TN + 2];   // transposed e tile

    const int t  = threadIdx.x;
    const int tx = t & 15;
    const int ty = t >> 4;
    const int lrow  = t >> 1;          // loader row 0..127
    const int lhalf = (t & 1) * 16;    // loader d-half

    for (int item = blockIdx.x; item < ITEMS; item += GRID_PERSIST) {
        const int mtile = item >> 4;
        const int split = item & (SPLITS - 1);
        const int m0 = mtile * TM;
        const int kbase = split * KS;

        float xsqv[8];
        #pragma unroll
        for (int q = 0; q < 4; q++) {
            xsqv[2 * q]     = g_xsq[m0 + 32 * q + 2 * ty];
            xsqv[2 * q + 1] = g_xsq[m0 + 32 * q + 2 * ty + 1];
        }

        float bestv[8];
        int   besti[8];
        #pragma unroll
        for (int i = 0; i < 8; i++) { bestv[i] = 3.4e38f; besti[i] = 0; }

        const unsigned long long zero2 = pack2(0.f, 0.f);

        for (int c = 0; c < NCHUNK; c++) {
            const int k0 = kbase + c * TN;

            unsigned long long accD[4][4], accA[4][4];
            #pragma unroll
            for (int q = 0; q < 4; q++)
                #pragma unroll
                for (int p = 0; p < 4; p++) { accD[q][p] = zero2; accA[q][p] = zero2; }

            // prefetch stage 0 into registers
            float4 gx[4], ge[4];
            #pragma unroll
            for (int i = 0; i < 4; i++) {
                gx[i] = *reinterpret_cast<const float4*>(&x[(size_t)(m0 + lrow) * DIM + lhalf + 4 * i]);
                ge[i] = *reinterpret_cast<const float4*>(&E[(size_t)(k0 + lrow) * DIM + lhalf + 4 * i]);
            }

            for (int s = 0; s < NSTAGE; s++) {
                __syncthreads();   // smem free (previous stage's readers done)
                #pragma unroll
                for (int i = 0; i < 4; i++) {
                    xs[lhalf + 4 * i + 0][lrow] = gx[i].x;
                    xs[lhalf + 4 * i + 1][lrow] = gx[i].y;
                    xs[lhalf + 4 * i + 2][lrow] = gx[i].z;
                    xs[lhalf + 4 * i + 3][lrow] = gx[i].w;
                    es[lhalf + 4 * i + 0][lrow] = ge[i].x;
                    es[lhalf + 4 * i + 1][lrow] = ge[i].y;
                    es[lhalf + 4 * i + 2][lrow] = ge[i].z;
                    es[lhalf + 4 * i + 3][lrow] = ge[i].w;
                }
                __syncthreads();
                if (s + 1 < NSTAGE) {   // prefetch next stage (hidden behind compute)
                    int d0 = (s + 1) * TD;
                    #pragma unroll
                    for (int i = 0; i < 4; i++) {
                        gx[i] = *reinterpret_cast<const float4*>(&x[(size_t)(m0 + lrow) * DIM + d0 + lhalf + 4 * i]);
                        ge[i] = *reinterpret_cast<const float4*>(&E[(size_t)(k0 + lrow) * DIM + d0 + lhalf + 4 * i]);
                    }
                }
                #pragma unroll 8
                for (int d = 0; d < TD; d++) {
                    unsigned long long xp[4];
                    #pragma unroll
                    for (int q = 0; q < 4; q++)
                        xp[q] = *reinterpret_cast<const unsigned long long*>(&xs[d][32 * q + 2 * ty]);
                    #pragma unroll
                    for (int p = 0; p < 4; p++) {
                        float2 e2 = *reinterpret_cast<const float2*>(&es[d][32 * p + 2 * tx]);
                        unsigned long long ef = pack2(e2.x, e2.y);
                        unsigned long long er = pack2(e2.y, e2.x);
                        #pragma unroll
                        for (int q = 0; q < 4; q++) {
                            accD[q][p] = fma2(xp[q], ef, accD[q][p]);
                            accA[q][p] = fma2(xp[q], er, accA[q][p]);
                        }
                    }
                }
            }

            // epilogue: dist = fl( fl(x_sq - 2*dot) + e_sq ); ascending k, strict <
            #pragma unroll
            for (int p = 0; p < 4; p++) {
                int c0 = k0 + 32 * p + 2 * tx;
                float eq0 = __ldg(&g_esq[c0]);
                float eq1 = __ldg(&g_esq[c0 + 1]);
                #pragma unroll
                for (int q = 0; q < 4; q++) {
                    float d00, d11, a01, a10;
                    unpack2(accD[q][p], d00, d11);   // (r0*c0, r1*c1)
                    unpack2(accA[q][p], a01, a10);   // (r0*c1, r1*c0)
                    // row r0 = 2q: col c0 then c1 (ascending)
                    float s0 = __fadd_rn(fmaf(-2.f, d00, xsqv[2 * q]), eq0);
                    if (s0 < bestv[2 * q]) { bestv[2 * q] = s0; besti[2 * q] = c0; }
                    float s1 = __fadd_rn(fmaf(-2.f, a01, xsqv[2 * q]), eq1);
                    if (s1 < bestv[2 * q]) { bestv[2 * q] = s1; besti[2 * q] = c0 + 1; }
                    // row r1 = 2q+1
                    float s2 = __fadd_rn(fmaf(-2.f, a10, xsqv[2 * q + 1]), eq0);
                    if (s2 < bestv[2 * q + 1]) { bestv[2 * q + 1] = s2; besti[2 * q + 1] = c0; }
                    float s3 = __fadd_rn(fmaf(-2.f, d11, xsqv[2 * q + 1]), eq1);
                    if (s3 < bestv[2 * q + 1]) { bestv[2 * q + 1] = s3; besti[2 * q + 1] = c0 + 1; }
                }
            }
        }

        // cross-thread reduction per item; alias dead tile buffers
        __syncthreads();
        float* rv = &xs[0][0];                      // [TM][16]
        int*   ri = reinterpret_cast<int*>(&es[0][0]);
        #pragma unroll
        for (int q = 0; q < 4; q++)
            #pragma unroll
            for (int s2 = 0; s2 < 2; s2++) {
                int row = 32 * q + 2 * ty + s2;
                rv[row * 16 + tx] = bestv[2 * q + s2];
                ri[row * 16 + tx] = besti[2 * q + s2];
            }
        __syncthreads();
        if (t < TM) {
            float bv = rv[t * 16];
            int   bi = ri[t * 16];
            #pragma unroll
            for (int j = 1; j < 16; j++) {
                float v = rv[t * 16 + j];
                int idx = ri[t * 16 + j];
                if (v < bv || (v == bv && idx < bi)) { bv = v; bi = idx; }
            }
            g_pval[split][m0 + t] = bv;
            g_pidx[split][m0 + t] = bi;
        }
        // next item's first __syncthreads() (before its smem stores) orders the
        // reduction reads above against buffer reuse.
    }
}

// ---------------- kernel 3: combine splits, gather, write q_st + indices ----------------
__global__ void vq_combine(const float* __restrict__ x, const float* __restrict__ E,
                           float* __restrict__ out) {
    int gw   = (blockIdx.x * blockDim.x + threadIdx.x) >> 5;  // one warp per token row
    int lane = threadIdx.x & 31;
    if (gw >= N_TOK) return;

    float bv = g_pval[0][gw];
    int   bi = g_pidx[0][gw];
    #pragma unroll
    for (int s = 1; s < SPLITS; s++) {
        float v = g_pval[s][gw];
        int idx = g_pidx[s][gw];
        if (v < bv || (v == bv && idx < bi)) { bv = v; bi = idx; }
    }

    const float* er = E + (size_t)bi * DIM;
    const float* xr = x + (size_t)gw * DIM;
    float* qr = out + (size_t)gw * DIM;
    float sq = 0.f;
    #pragma unroll
    for (int d = lane; d < DIM; d += 32) {
        float e  = er[d];
        float xv = xr[d];
        qr[d] = __fadd_rn(xv, __fadd_rn(e, -xv));  // straight-through: fl(x + fl(q - x))
        float df = __fadd_rn(xv, -e);
        sq = __fadd_rn(sq, __fmul_rn(df, df));
    }
    #pragma unroll
    for (int o = 16; o > 0; o >>= 1) sq = __fadd_rn(sq, __shfl_xor_sync(0xffffffffu, sq, o));
    if (lane == 0) {
        g_rowsq[gw] = sq;
        out[(size_t)N_TOK * DIM + gw] = (float)bi;   // indices as float32
    }
}

// ---------------- kernel 4: deterministic loss reduction ----------------
__global__ void vq_loss(float* __restrict__ out) {
    __shared__ float red[256];
    int t = threadIdx.x;
    float s = 0.f;
    for (int i = t; i < N_TOK; i += 256) s += g_rowsq[i];
    red[t] = s;
    __syncthreads();
    #pragma unroll
    for (int o = 128; o > 0; o >>= 1) {
        if (t < o) red[t] += red[t + o];
        __syncthreads();
    }
    if (t == 0) {
        float mse = red[0] / (float)((size_t)N_TOK * DIM);
        size_t base = (size_t)N_TOK * DIM + N_TOK;
        out[base + 0] = 0.25f * mse;   // commitment_loss
        out[base + 1] = mse;           // codebook_loss
        out[base + 2] = 1.25f * mse;   // total_loss
    }
}

// ---------------- entry point ----------------
extern "C" void kernel_launch(void* const* d_in, const int* in_sizes, int n_in,
                              void* d_out, int out_size) {
    (void)in_sizes; (void)n_in; (void)out_size;
    const float* x = (const float*)d_in[0];   // [32*256, 512]
    const float* E = (const float*)d_in[1];   // [8192, 512]
    float* out = (float*)d_out;

    vq_esq<<<K_CODES * 32 / 256, 256>>>(E);
    vq_xsq<<<N_TOK * 32 / 256, 256>>>(x);
    vq_argmin<<<GRID_PERSIST, 256>>>(x, E);
    vq_combine<<<N_TOK * 32 / 256, 256>>>(x, E, out);
    vq_loss<<<1, 256>>>(out);
}

// round 11
// speedup vs baseline: 1.2133x; 1.1607x over previous
#include <cuda_runtime.h>
#include <cstdint>

// Problem constants (fixed by the dataset: x [32,256,512], embeddings [8192,512])
#define N_TOK   8192
#define K_CODES 8192
#define DIM     512

// Argmin-GEMM tiling: persistent blocks (2 CTAs/SM), items = (mtile, split)
#define TM 128       // token rows per item
#define TN 128       // codes per k-chunk
#define TD 32        // D-slice per smem stage
#define SPLITS 32    // K splits (item granularity for load balance)
#define KS (K_CODES / SPLITS)        // 256
#define NCHUNK (KS / TN)             // 2
#define NSTAGE (DIM / TD)            // 16
#define MTILES (N_TOK / TM)          // 64
#define ITEMS (MTILES * SPLITS)      // 2048
#define GRID_PERSIST 296             // 2 CTAs per SM x 148 SMs

// ---------------- device scratch (no allocations allowed) ----------------
// Referenced ONLY from device code (host-side use of a __device__ symbol is the
// host shadow address -> UVM pool allocation -> harness mem-guard failure).
__device__ float g_esq[K_CODES];
__device__ float g_xsq[N_TOK];
__device__ float g_pval[SPLITS][N_TOK];
__device__ int   g_pidx[SPLITS][N_TOK];
__device__ float g_rowsq[N_TOK];

// ---------------- packed f32x2 helpers (sm_100a Blackwell) ----------------
// Each 32-bit lane of fma.rn.f32x2 is an independent IEEE fp32 FMA, so a packed
// accumulator chain over ascending d is bit-identical to a scalar FFMA chain.
__device__ __forceinline__ unsigned long long pack2(float a, float b) {
    unsigned long long r;
    asm("mov.b64 %0, {%1, %2};" : "=l"(r) : "f"(a), "f"(b));
    return r;
}
__device__ __forceinline__ void unpack2(unsigned long long v, float& a, float& b) {
    asm("mov.b64 {%0, %1}, %2;" : "=f"(a), "=f"(b) : "l"(v));
}
__device__ __forceinline__ unsigned long long fma2(unsigned long long a,
                                                   unsigned long long b,
                                                   unsigned long long c) {
    unsigned long long d;
    asm("fma.rn.f32x2 %0, %1, %2, %3;" : "=l"(d) : "l"(a), "l"(b), "l"(c));
    return d;
}

// ---------------- kernel 1a: e_sq[k] = sum_d E[k][d]^2 ----------------
// XLA row-reduce replica: lane-strided ascending accumulation, NON-FUSED
// mul+add, butterfly tree. (Verified bit-exact in R9/R10.)
__global__ void vq_esq(const float* __restrict__ E) {
    int w = (blockIdx.x * blockDim.x + threadIdx.x) >> 5;
    int lane = threadIdx.x & 31;
    if (w >= K_CODES) return;
    const float* row = E + (size_t)w * DIM;
    float s = 0.f;
    #pragma unroll
    for (int d = lane; d < DIM; d += 32) {
        float v = __ldg(row + d);
        s = __fadd_rn(s, __fmul_rn(v, v));
    }
    #pragma unroll
    for (int o = 16; o > 0; o >>= 1) s = __fadd_rn(s, __shfl_xor_sync(0xffffffffu, s, o));
    if (lane == 0) g_esq[w] = s;
}

// ---------------- kernel 1b: x_sq[n] = sum_d x[n][d]^2 ----------------
__global__ void vq_xsq(const float* __restrict__ x) {
    int w = (blockIdx.x * blockDim.x + threadIdx.x) >> 5;
    int lane = threadIdx.x & 31;
    if (w >= N_TOK) return;
    const float* row = x + (size_t)w * DIM;
    float s = 0.f;
    #pragma unroll
    for (int d = lane; d < DIM; d += 32) {
        float v = __ldg(row + d);
        s = __fadd_rn(s, __fmul_rn(v, v));
    }
    #pragma unroll
    for (int o = 16; o > 0; o >>= 1) s = __fadd_rn(s, __shfl_xor_sync(0xffffffffu, s, o));
    if (lane == 0) g_xsq[w] = s;
}

// ---------------- kernel 2: persistent fused fp32-dot + argmin ----------------
// 296 blocks (2/SM) x 256 threads, static round-robin over 2048 (mtile, split)
// items. Thread tile 8x8 via pair-x-pair packed FMA:
//   accD[q][p] lanes = (r0*c0, r1*c1), accA[q][p] lanes = (r0*c1, r1*c0)
// Every lane is a serial ascending-d fp32 FMA chain -> bit-identical.
// dist[n][k] = fl( fl(x_sq[n] - 2*dot) + e_sq[k] ), first-index tie-break.
__global__ __launch_bounds__(256, 2) void vq_argmin(const float* __restrict__ x,
                                                    const float* __restrict__ E) {
    __shared__ float xs[TD][TM + 2];   // transposed x tile (stride 130, even)
    __shared__ float es[TD][TN + 2];   // transposed e tile

    const int t  = threadIdx.x;
    const int tx = t & 15;
    const int ty = t >> 4;
    const int lrow  = t >> 1;          // loader row 0..127
    const int lhalf = (t & 1) * 16;    // loader d-half

    for (int item = blockIdx.x; item < ITEMS; item += GRID_PERSIST) {
        const int mtile = item >> 5;               // /SPLITS
        const int split = item & (SPLITS - 1);
        const int m0 = mtile * TM;
        const int kbase = split * KS;

        float xsqv[8];
        #pragma unroll
        for (int q = 0; q < 4; q++) {
            xsqv[2 * q]     = g_xsq[m0 + 32 * q + 2 * ty];
            xsqv[2 * q + 1] = g_xsq[m0 + 32 * q + 2 * ty + 1];
        }

        float bestv[8];
        int   besti[8];
        #pragma unroll
        for (int i = 0; i < 8; i++) { bestv[i] = 3.4e38f; besti[i] = 0; }

        const unsigned long long zero2 = pack2(0.f, 0.f);

        for (int c = 0; c < NCHUNK; c++) {
            const int k0 = kbase + c * TN;

            unsigned long long accD[4][4], accA[4][4];
            #pragma unroll
            for (int q = 0; q < 4; q++)
                #pragma unroll
                for (int p = 0; p < 4; p++) { accD[q][p] = zero2; accA[q][p] = zero2; }

            for (int s = 0; s < NSTAGE; s++) {
                const int d0 = s * TD;
                __syncthreads();   // previous stage's readers done
                // direct G->S (L2-resident); co-resident CTA hides the latency
                #pragma unroll
                for (int i = 0; i < 4; i++) {
                    float4 gx = *reinterpret_cast<const float4*>(&x[(size_t)(m0 + lrow) * DIM + d0 + lhalf + 4 * i]);
                    xs[lhalf + 4 * i + 0][lrow] = gx.x;
                    xs[lhalf + 4 * i + 1][lrow] = gx.y;
                    xs[lhalf + 4 * i + 2][lrow] = gx.z;
                    xs[lhalf + 4 * i + 3][lrow] = gx.w;
                    float4 ge = *reinterpret_cast<const float4*>(&E[(size_t)(k0 + lrow) * DIM + d0 + lhalf + 4 * i]);
                    es[lhalf + 4 * i + 0][lrow] = ge.x;
                    es[lhalf + 4 * i + 1][lrow] = ge.y;
                    es[lhalf + 4 * i + 2][lrow] = ge.z;
                    es[lhalf + 4 * i + 3][lrow] = ge.w;
                }
                __syncthreads();
                #pragma unroll 8
                for (int d = 0; d < TD; d++) {
                    unsigned long long xp[4];
                    #pragma unroll
                    for (int q = 0; q < 4; q++)
                        xp[q] = *reinterpret_cast<const unsigned long long*>(&xs[d][32 * q + 2 * ty]);
                    #pragma unroll
                    for (int p = 0; p < 4; p++) {
                        float2 e2 = *reinterpret_cast<const float2*>(&es[d][32 * p + 2 * tx]);
                        unsigned long long ef = pack2(e2.x, e2.y);
                        unsigned long long er = pack2(e2.y, e2.x);
                        #pragma unroll
                        for (int q = 0; q < 4; q++) {
                            accD[q][p] = fma2(xp[q], ef, accD[q][p]);
                            accA[q][p] = fma2(xp[q], er, accA[q][p]);
                        }
                    }
                }
            }

            // epilogue: dist = fl( fl(x_sq - 2*dot) + e_sq ); ascending k, strict <
            #pragma unroll
            for (int p = 0; p < 4; p++) {
                int c0 = k0 + 32 * p + 2 * tx;
                float eq0 = __ldg(&g_esq[c0]);
                float eq1 = __ldg(&g_esq[c0 + 1]);
                #pragma unroll
                for (int q = 0; q < 4; q++) {
                    float d00, d11, a01, a10;
                    unpack2(accD[q][p], d00, d11);   // (r0*c0, r1*c1)
                    unpack2(accA[q][p], a01, a10);   // (r0*c1, r1*c0)
                    float s0 = __fadd_rn(fmaf(-2.f, d00, xsqv[2 * q]), eq0);
                    if (s0 < bestv[2 * q]) { bestv[2 * q] = s0; besti[2 * q] = c0; }
                    float s1 = __fadd_rn(fmaf(-2.f, a01, xsqv[2 * q]), eq1);
                    if (s1 < bestv[2 * q]) { bestv[2 * q] = s1; besti[2 * q] = c0 + 1; }
                    float s2 = __fadd_rn(fmaf(-2.f, a10, xsqv[2 * q + 1]), eq0);
                    if (s2 < bestv[2 * q + 1]) { bestv[2 * q + 1] = s2; besti[2 * q + 1] = c0; }
                    float s3 = __fadd_rn(fmaf(-2.f, d11, xsqv[2 * q + 1]), eq1);
                    if (s3 < bestv[2 * q + 1]) { bestv[2 * q + 1] = s3; besti[2 * q + 1] = c0 + 1; }
                }
            }
        }

        // cross-thread reduction per item; alias dead tile buffers
        __syncthreads();
        float* rv = &xs[0][0];                      // [TM][16]
        int*   ri = reinterpret_cast<int*>(&es[0][0]);
        #pragma unroll
        for (int q = 0; q < 4; q++)
            #pragma unroll
            for (int s2 = 0; s2 < 2; s2++) {
                int row = 32 * q + 2 * ty + s2;
                rv[row * 16 + tx] = bestv[2 * q + s2];
                ri[row * 16 + tx] = besti[2 * q + s2];
            }
        __syncthreads();
        if (t < TM) {
            float bv = rv[t * 16];
            int   bi = ri[t * 16];
            #pragma unroll
            for (int j = 1; j < 16; j++) {
                float v = rv[t * 16 + j];
                int idx = ri[t * 16 + j];
                if (v < bv || (v == bv && idx < bi)) { bv = v; bi = idx; }
            }
            g_pval[split][m0 + t] = bv;
            g_pidx[split][m0 + t] = bi;
        }
        // next item's first __syncthreads() (before its smem stores) orders the
        // reduction reads above against buffer reuse.
    }
}

// ---------------- kernel 3: combine splits, gather, write q_st + indices ----------------
__global__ void vq_combine(const float* __restrict__ x, const float* __restrict__ E,
                           float* __restrict__ out) {
    int gw   = (blockIdx.x * blockDim.x + threadIdx.x) >> 5;  // one warp per token row
    int lane = threadIdx.x & 31;
    if (gw >= N_TOK) return;

    float bv = g_pval[0][gw];
    int   bi = g_pidx[0][gw];
    #pragma unroll
    for (int s = 1; s < SPLITS; s++) {
        float v = g_pval[s][gw];
        int idx = g_pidx[s][gw];
        if (v < bv || (v == bv && idx < bi)) { bv = v; bi = idx; }
    }

    const float* er = E + (size_t)bi * DIM;
    const float* xr = x + (size_t)gw * DIM;
    float* qr = out + (size_t)gw * DIM;
    float sq = 0.f;
    #pragma unroll
    for (int d = lane; d < DIM; d += 32) {
        float e  = er[d];
        float xv = xr[d];
        qr[d] = __fadd_rn(xv, __fadd_rn(e, -xv));  // straight-through: fl(x + fl(q - x))
        float df = __fadd_rn(xv, -e);
        sq = __fadd_rn(sq, __fmul_rn(df, df));
    }
    #pragma unroll
    for (int o = 16; o > 0; o >>= 1) sq = __fadd_rn(sq, __shfl_xor_sync(0xffffffffu, sq, o));
    if (lane == 0) {
        g_rowsq[gw] = sq;
        out[(size_t)N_TOK * DIM + gw] = (float)bi;   // indices as float32
    }
}

// ---------------- kernel 4: deterministic loss reduction ----------------
__global__ void vq_loss(float* __restrict__ out) {
    __shared__ float red[256];
    int t = threadIdx.x;
    float s = 0.f;
    for (int i = t; i < N_TOK; i += 256) s += g_rowsq[i];
    red[t] = s;
    __syncthreads();
    #pragma unroll
    for (int o = 128; o > 0; o >>= 1) {
        if (t < o) red[t] += red[t + o];
        __syncthreads();
    }
    if (t == 0) {
        float mse = red[0] / (float)((size_t)N_TOK * DIM);
        size_t base = (size_t)N_TOK * DIM + N_TOK;
        out[base + 0] = 0.25f * mse;   // commitment_loss
        out[base + 1] = mse;           // codebook_loss
        out[base + 2] = 1.25f * mse;   // total_loss
    }
}

// ---------------- entry point ----------------
extern "C" void kernel_launch(void* const* d_in, const int* in_sizes, int n_in,
                              void* d_out, int out_size) {
    (void)in_sizes; (void)n_in; (void)out_size;
    const float* x = (const float*)d_in[0];   // [32*256, 512]
    const float* E = (const float*)d_in[1];   // [8192, 512]
    float* out = (float*)d_out;

    vq_esq<<<K_CODES * 32 / 256, 256>>>(E);
    vq_xsq<<<N_TOK * 32 / 256, 256>>>(x);
    vq_argmin<<<GRID_PERSIST, 256>>>(x, E);
    vq_combine<<<N_TOK * 32 / 256, 256>>>(x, E, out);
    vq_loss<<<1, 256>>>(out);
}